// round 2
// baseline (speedup 1.0000x reference)
#include <cuda_runtime.h>
#include <math.h>

#define NMAX 50000
#define FDIM 96
#define EMAX 800000
#define DEPTH 3
#define OUTC 384   // (DEPTH+1)*FDIM
#define LEAKY 0.2f

// ---------------- device scratch (no allocs allowed) ----------------
__device__ float g_fa[NMAX * FDIM];
__device__ float g_fb[NMAX * FDIM];
__device__ float4 g_eterm[NMAX];          // es0, es1, en0, en1
__device__ int   g_deg[NMAX];
__device__ int   g_rowstart[NMAX + 1];
__device__ int   g_cursor[NMAX];
__device__ int   g_csrcol[EMAX];
__device__ int   g_is64;                  // 1 if index arrays are int64

__device__ __forceinline__ float leaky(float x) {
    return x > 0.0f ? x : LEAKY * x;
}

// read index i from an array that is either int32 or int64
__device__ __forceinline__ int fetch_idx(const void* p, long i, int is64) {
    if (is64) return (int)((const long long*)p)[i];
    return ((const int*)p)[i];
}

// ---------------- dtype detection ----------------
// For int64 data viewed as int32 words, all odd words are high halves == 0.
// For int32 data, odd words are random indices -> virtually never all zero.
__global__ void k_detect(const int* __restrict__ adj_words, int nwords) {
    int acc = 0;
    int lim = min(nwords, 4096);
    for (int i = 1; i < lim; i += 2) acc |= adj_words[i];
    g_is64 = (acc == 0) ? 1 : 0;
}

// ---------------- zero deg + feature buffer A ----------------
__global__ void k_zero(int n) {
    int total = n * FDIM;
    for (int i = blockIdx.x * blockDim.x + threadIdx.x; i < total;
         i += gridDim.x * blockDim.x) {
        g_fa[i] = 0.0f;
        if (i < n) g_deg[i] = 0;
    }
}

// ---------------- CSR build ----------------
__global__ void k_hist(const void* __restrict__ adj, int e, int n) {
    int is64 = g_is64;
    for (int i = blockIdx.x * blockDim.x + threadIdx.x; i < e;
         i += gridDim.x * blockDim.x) {
        int r = fetch_idx(adj, 2L * i, is64);
        if ((unsigned)r < (unsigned)n) atomicAdd(&g_deg[r], 1);
    }
}

__global__ void k_scan(int n) {
    __shared__ int part[1024];
    const int t = threadIdx.x;
    const int chunk = (n + 1023) / 1024;
    int b0 = t * chunk;
    int b1 = min(b0 + chunk, n);
    int s = 0;
    for (int i = b0; i < b1; i++) s += g_deg[i];
    part[t] = s;
    __syncthreads();
    for (int off = 1; off < 1024; off <<= 1) {
        int v = (t >= off) ? part[t - off] : 0;
        __syncthreads();
        part[t] += v;
        __syncthreads();
    }
    int base = (t == 0) ? 0 : part[t - 1];
    for (int i = b0; i < b1; i++) {
        g_rowstart[i] = base;
        g_cursor[i]   = base;
        base += g_deg[i];
    }
    if (t == 1023) g_rowstart[n] = part[1023];
}

__global__ void k_scatter(const void* __restrict__ adj, int e, int n) {
    int is64 = g_is64;
    for (int i = blockIdx.x * blockDim.x + threadIdx.x; i < e;
         i += gridDim.x * blockDim.x) {
        int r = fetch_idx(adj, 2L * i, is64);
        int c = fetch_idx(adj, 2L * i + 1, is64);
        if ((unsigned)r >= (unsigned)n) continue;
        if ((unsigned)c >= (unsigned)n) c = 0;
        int pos = atomicAdd(&g_cursor[r], 1);
        if (pos < EMAX) g_csrcol[pos] = c;
    }
}

// ---------------- initial features: scatter adj_self_val * node_f ----------------
__global__ void k_init(const float* __restrict__ node_f,
                       const void* __restrict__ sidx,
                       const float* __restrict__ sval, int n) {
    int gw = (blockIdx.x * blockDim.x + threadIdx.x) >> 5;
    int lane = threadIdx.x & 31;
    if (gw >= n) return;
    int is64 = g_is64;
    int r = fetch_idx(sidx, 2L * gw, is64);
    int c = fetch_idx(sidx, 2L * gw + 1, is64);
    if ((unsigned)r >= (unsigned)n || (unsigned)c >= (unsigned)n) return;
    float v = sval[gw];
    const float* src = node_f + (long)c * FDIM;
    float* dst = g_fa + (long)r * FDIM;
#pragma unroll
    for (int k = 0; k < 3; k++) {
        atomicAdd(&dst[lane + 32 * k], v * src[lane + 32 * k]);
    }
}

// relu in place on g_fa + write slice 0 of output
__global__ void k_relu_copy(float* __restrict__ out, int n) {
    int total = n * FDIM;
    for (int i = blockIdx.x * blockDim.x + threadIdx.x; i < total;
         i += gridDim.x * blockDim.x) {
        float v = g_fa[i];
        v = fmaxf(v, 0.0f);
        g_fa[i] = v;
        int row = i / FDIM;
        int f   = i - row * FDIM;
        out[(long)row * OUTC + f] = v;
    }
}

// ---------------- per-node attention logits ----------------
// one warp per node; computes es(h0,h1), en(h0,h1)
__global__ void k_eterm(int src, const float* __restrict__ as,
                        const float* __restrict__ an, int n) {
    int gw = (blockIdx.x * blockDim.x + threadIdx.x) >> 5;
    int lane = threadIdx.x & 31;
    if (gw >= n) return;
    const float* feat = src ? g_fb : g_fa;
    const float* fr = feat + (long)gw * FDIM;
    float f0 = fr[lane], f1 = fr[lane + 32], f2 = fr[lane + 64];

    float s0 = f0 * as[lane]      + f1 * as[lane + 32]      + f2 * as[lane + 64];
    float s1 = f0 * as[96 + lane] + f1 * as[96 + lane + 32] + f2 * as[96 + lane + 64];
    float n0 = f0 * an[lane]      + f1 * an[lane + 32]      + f2 * an[lane + 64];
    float n1 = f0 * an[96 + lane] + f1 * an[96 + lane + 32] + f2 * an[96 + lane + 64];
#pragma unroll
    for (int off = 16; off > 0; off >>= 1) {
        s0 += __shfl_xor_sync(0xffffffffu, s0, off);
        s1 += __shfl_xor_sync(0xffffffffu, s1, off);
        n0 += __shfl_xor_sync(0xffffffffu, n0, off);
        n1 += __shfl_xor_sync(0xffffffffu, n1, off);
    }
    if (lane == 0) g_eterm[gw] = make_float4(s0, s1, n0, n1);
}

// ---------------- layer: softmax + aggregate (both heads fused) ----------------
// one warp per destination row
__global__ void k_layer(int src, float* __restrict__ out, int layer, int n) {
    int gw = (blockIdx.x * blockDim.x + threadIdx.x) >> 5;
    int lane = threadIdx.x & 31;
    if (gw >= n) return;
    const float* feat = src ? g_fb : g_fa;
    float* feat_out   = src ? g_fa : g_fb;

    int start = g_rowstart[gw];
    int end   = g_rowstart[gw + 1];

    float4 er = g_eterm[gw];
    float es0 = er.x, es1 = er.y;

    // pass 1: max
    float m0 = -INFINITY, m1 = -INFINITY;
    for (int j = start + lane; j < end; j += 32) {
        int c = g_csrcol[j];
        float4 ec = g_eterm[c];
        m0 = fmaxf(m0, leaky(es0 + ec.z));
        m1 = fmaxf(m1, leaky(es1 + ec.w));
    }
#pragma unroll
    for (int off = 16; off > 0; off >>= 1) {
        m0 = fmaxf(m0, __shfl_xor_sync(0xffffffffu, m0, off));
        m1 = fmaxf(m1, __shfl_xor_sync(0xffffffffu, m1, off));
    }

    // pass 2: sum of exp
    float sum0 = 0.0f, sum1 = 0.0f;
    for (int j = start + lane; j < end; j += 32) {
        int c = g_csrcol[j];
        float4 ec = g_eterm[c];
        sum0 += __expf(leaky(es0 + ec.z) - m0);
        sum1 += __expf(leaky(es1 + ec.w) - m1);
    }
#pragma unroll
    for (int off = 16; off > 0; off >>= 1) {
        sum0 += __shfl_xor_sync(0xffffffffu, sum0, off);
        sum1 += __shfl_xor_sync(0xffffffffu, sum1, off);
    }

    // pass 3: weighted aggregation, both heads share the feature gather
    float a0[3] = {0.f, 0.f, 0.f};
    float a1[3] = {0.f, 0.f, 0.f};
    for (int j = start; j < end; j++) {
        int c = g_csrcol[j];               // broadcast load
        float4 ec = g_eterm[c];            // broadcast load
        float w0 = __expf(leaky(es0 + ec.z) - m0);
        float w1 = __expf(leaky(es1 + ec.w) - m1);
        const float* fr = feat + (long)c * FDIM;
#pragma unroll
        for (int k = 0; k < 3; k++) {
            float v = fr[lane + 32 * k];
            a0[k] += w0 * v;
            a1[k] += w1 * v;
        }
    }
    float inv0 = sum0 > 0.0f ? 1.0f / sum0 : 0.0f;
    float inv1 = sum1 > 0.0f ? 1.0f / sum1 : 0.0f;

    float* fo = feat_out + (long)gw * FDIM;
    float* oo = out + (long)gw * OUTC + (layer + 1) * FDIM;
#pragma unroll
    for (int k = 0; k < 3; k++) {
        float v = 0.5f * (a0[k] * inv0 + a1[k] * inv1);
        v = fmaxf(v, 0.0f);
        fo[lane + 32 * k] = v;
        oo[lane + 32 * k] = v;
    }
}

// ---------------- launch ----------------
extern "C" void kernel_launch(void* const* d_in, const int* in_sizes, int n_in,
                              void* d_out, int out_size) {
    const float* node_f = (const float*)d_in[0];
    const void*  adj    = d_in[1];
    const void*  sidx   = d_in[2];
    const float* sval   = (const float*)d_in[3];
    const float* as_k   = (const float*)d_in[4];
    const float* an_k   = (const float*)d_in[5];
    float*       out    = (float*)d_out;

    int n = in_sizes[0] / FDIM;
    int e = in_sizes[1] / 2;
    if (n > NMAX) n = NMAX;
    if (e > EMAX) e = EMAX;

    const int T = 256;
    int gridNF = (n * FDIM + T - 1) / T;
    int gridE  = (e + T - 1) / T;
    int gridW  = (n + (T / 32) - 1) / (T / 32);   // warp-per-row kernels

    k_detect<<<1, 1>>>((const int*)adj, in_sizes[1]);
    k_zero<<<gridNF, T>>>(n);
    k_hist<<<gridE, T>>>(adj, e, n);
    k_scan<<<1, 1024>>>(n);
    k_scatter<<<gridE, T>>>(adj, e, n);
    k_init<<<gridW, T>>>(node_f, sidx, sval, n);
    k_relu_copy<<<gridNF, T>>>(out, n);

    int src = 0;   // 0 => features in g_fa
    for (int d = 0; d < DEPTH; d++) {
        k_eterm<<<gridW, T>>>(src, as_k, an_k, n);
        k_layer<<<gridW, T>>>(src, out, d, n);
        src ^= 1;
    }
}

// round 4
// speedup vs baseline: 1.6510x; 1.6510x over previous
#include <cuda_runtime.h>
#include <math.h>

#define NMAX 50000
#define FDIM 96
#define EMAX 800000
#define DEPTH 3
#define OUTC 384   // (DEPTH+1)*FDIM
#define LEAKY 0.2f

// ---------------- device scratch ----------------
__device__ float g_fa[NMAX * FDIM];
__device__ float g_fb[NMAX * FDIM];
__device__ float4 g_eterm[NMAX];          // es0, es1, en0, en1
__device__ int   g_deg[NMAX];
__device__ int   g_rowstart[NMAX];
__device__ int   g_cursor[NMAX];
__device__ int   g_csrcol[EMAX];
__device__ int   g_total;
__device__ int   g_is64;

__device__ __forceinline__ float leaky(float x) {
    return x > 0.0f ? x : LEAKY * x;
}

__device__ __forceinline__ int fetch_idx(const void* p, long i, int is64) {
    if (is64) return (int)((const long long*)p)[i];
    return ((const int*)p)[i];
}

// ---------------- dtype detection (parallel) ----------------
// int64 viewed as int32 words: odd words (high halves) all zero.
__global__ void k_detect(const int* __restrict__ adj_words, int nwords) {
    __shared__ int sh[1024];
    int t = threadIdx.x;
    int acc = 0;
    int lim = min(nwords, 65536);
    for (int i = 1 + 2 * t; i < lim; i += 2048) acc |= adj_words[i];
    sh[t] = acc;
    __syncthreads();
    for (int off = 512; off > 0; off >>= 1) {
        if (t < off) sh[t] |= sh[t + off];
        __syncthreads();
    }
    if (t == 0) g_is64 = (sh[0] == 0) ? 1 : 0;
}

__global__ void k_zerodeg(int n) {
    int gid = blockIdx.x * blockDim.x + threadIdx.x;
    for (int i = gid; i < n; i += gridDim.x * blockDim.x)
        g_deg[i] = 0;
    if (gid == 0) g_total = 0;
}

// ---------------- CSR build (no scan: atomic slice assignment) ------------
__global__ void k_hist(const void* __restrict__ adj, int e, int n) {
    int is64 = g_is64;
    for (int i = blockIdx.x * blockDim.x + threadIdx.x; i < e;
         i += gridDim.x * blockDim.x) {
        int r = fetch_idx(adj, 2L * i, is64);
        if ((unsigned)r < (unsigned)n) atomicAdd(&g_deg[r], 1);
    }
}

// each row grabs a contiguous slice [start, start+deg) of g_csrcol
__global__ void k_assign(int n) {
    for (int i = blockIdx.x * blockDim.x + threadIdx.x; i < n;
         i += gridDim.x * blockDim.x) {
        int d = g_deg[i];
        int base = atomicAdd(&g_total, d);
        g_rowstart[i] = base;
        g_cursor[i]   = base;
    }
}

__global__ void k_scatter(const void* __restrict__ adj, int e, int n) {
    int is64 = g_is64;
    for (int i = blockIdx.x * blockDim.x + threadIdx.x; i < e;
         i += gridDim.x * blockDim.x) {
        int r = fetch_idx(adj, 2L * i, is64);
        int c = fetch_idx(adj, 2L * i + 1, is64);
        if ((unsigned)r >= (unsigned)n) continue;
        if ((unsigned)c >= (unsigned)n) c = 0;
        int pos = atomicAdd(&g_cursor[r], 1);
        if (pos < EMAX) g_csrcol[pos] = c;
    }
}

// ---------------- initial features (diag rows unique -> direct store) -----
// features = relu(val * node_f[c]) -> g_fa and out slice 0
__global__ void k_init(const float* __restrict__ node_f,
                       const void* __restrict__ sidx,
                       const float* __restrict__ sval,
                       float* __restrict__ out, int n) {
    int gw = (blockIdx.x * blockDim.x + threadIdx.x) >> 5;
    int lane = threadIdx.x & 31;
    if (gw >= n) return;
    int is64 = g_is64;
    int r = fetch_idx(sidx, 2L * gw, is64);
    int c = fetch_idx(sidx, 2L * gw + 1, is64);
    if ((unsigned)r >= (unsigned)n || (unsigned)c >= (unsigned)n) return;
    float v = sval[gw];
    const float* src = node_f + (long)c * FDIM;
    float* dst = g_fa + (long)r * FDIM;
    float* oo  = out + (long)r * OUTC;
#pragma unroll
    for (int k = 0; k < 3; k++) {
        float x = fmaxf(v * src[lane + 32 * k], 0.0f);
        dst[lane + 32 * k] = x;
        oo[lane + 32 * k]  = x;
    }
}

// ---------------- per-node attention logits ----------------
__global__ void k_eterm(int src, const float* __restrict__ as,
                        const float* __restrict__ an, int n) {
    int gw = (blockIdx.x * blockDim.x + threadIdx.x) >> 5;
    int lane = threadIdx.x & 31;
    if (gw >= n) return;
    const float* feat = src ? g_fb : g_fa;
    const float* fr = feat + (long)gw * FDIM;
    float f0 = fr[lane], f1 = fr[lane + 32], f2 = fr[lane + 64];

    float s0 = f0 * as[lane]      + f1 * as[lane + 32]      + f2 * as[lane + 64];
    float s1 = f0 * as[96 + lane] + f1 * as[96 + lane + 32] + f2 * as[96 + lane + 64];
    float n0 = f0 * an[lane]      + f1 * an[lane + 32]      + f2 * an[lane + 64];
    float n1 = f0 * an[96 + lane] + f1 * an[96 + lane + 32] + f2 * an[96 + lane + 64];
#pragma unroll
    for (int off = 16; off > 0; off >>= 1) {
        s0 += __shfl_xor_sync(0xffffffffu, s0, off);
        s1 += __shfl_xor_sync(0xffffffffu, s1, off);
        n0 += __shfl_xor_sync(0xffffffffu, n0, off);
        n1 += __shfl_xor_sync(0xffffffffu, n1, off);
    }
    if (lane == 0) g_eterm[gw] = make_float4(s0, s1, n0, n1);
}

// ---------------- layer: softmax + aggregate (2 heads fused, 2-pass) ------
__global__ void k_layer(int src, float* __restrict__ out, int layer, int n) {
    int gw = (blockIdx.x * blockDim.x + threadIdx.x) >> 5;
    int lane = threadIdx.x & 31;
    if (gw >= n) return;
    const float* feat = src ? g_fb : g_fa;
    float* feat_out   = src ? g_fa : g_fb;

    int start = g_rowstart[gw];
    int end   = start + g_deg[gw];

    float4 er = g_eterm[gw];
    float es0 = er.x, es1 = er.y;

    // pass 1: max
    float m0 = -INFINITY, m1 = -INFINITY;
    for (int j = start + lane; j < end; j += 32) {
        int c = g_csrcol[j];
        float4 ec = g_eterm[c];
        m0 = fmaxf(m0, leaky(es0 + ec.z));
        m1 = fmaxf(m1, leaky(es1 + ec.w));
    }
#pragma unroll
    for (int off = 16; off > 0; off >>= 1) {
        m0 = fmaxf(m0, __shfl_xor_sync(0xffffffffu, m0, off));
        m1 = fmaxf(m1, __shfl_xor_sync(0xffffffffu, m1, off));
    }

    // pass 2: sum of exp
    float sum0 = 0.0f, sum1 = 0.0f;
    for (int j = start + lane; j < end; j += 32) {
        int c = g_csrcol[j];
        float4 ec = g_eterm[c];
        sum0 += __expf(leaky(es0 + ec.z) - m0);
        sum1 += __expf(leaky(es1 + ec.w) - m1);
    }
#pragma unroll
    for (int off = 16; off > 0; off >>= 1) {
        sum0 += __shfl_xor_sync(0xffffffffu, sum0, off);
        sum1 += __shfl_xor_sync(0xffffffffu, sum1, off);
    }

    // pass 3: weighted aggregation; both heads share the feature gather
    float a0[3] = {0.f, 0.f, 0.f};
    float a1[3] = {0.f, 0.f, 0.f};
    for (int j = start; j < end; j++) {
        int c = g_csrcol[j];               // broadcast
        float4 ec = g_eterm[c];            // broadcast
        float w0 = __expf(leaky(es0 + ec.z) - m0);
        float w1 = __expf(leaky(es1 + ec.w) - m1);
        const float* fr = feat + (long)c * FDIM;
#pragma unroll
        for (int k = 0; k < 3; k++) {
            float v = fr[lane + 32 * k];
            a0[k] += w0 * v;
            a1[k] += w1 * v;
        }
    }
    float inv0 = sum0 > 0.0f ? 1.0f / sum0 : 0.0f;
    float inv1 = sum1 > 0.0f ? 1.0f / sum1 : 0.0f;

    float* fo = feat_out + (long)gw * FDIM;
    float* oo = out + (long)gw * OUTC + (layer + 1) * FDIM;
#pragma unroll
    for (int k = 0; k < 3; k++) {
        float v = 0.5f * (a0[k] * inv0 + a1[k] * inv1);
        v = fmaxf(v, 0.0f);
        fo[lane + 32 * k] = v;
        oo[lane + 32 * k] = v;
    }
}

// ---------------- launch ----------------
extern "C" void kernel_launch(void* const* d_in, const int* in_sizes, int n_in,
                              void* d_out, int out_size) {
    const float* node_f = (const float*)d_in[0];
    const void*  adj    = d_in[1];
    const void*  sidx   = d_in[2];
    const float* sval   = (const float*)d_in[3];
    const float* as_k   = (const float*)d_in[4];
    const float* an_k   = (const float*)d_in[5];
    float*       out    = (float*)d_out;

    int n = in_sizes[0] / FDIM;
    int e = in_sizes[1] / 2;
    if (n > NMAX) n = NMAX;
    if (e > EMAX) e = EMAX;

    const int T = 256;
    int gridN = (n + T - 1) / T;
    int gridE = (e + T - 1) / T;
    int gridW = (n + (T / 32) - 1) / (T / 32);

    k_detect<<<1, 1024>>>((const int*)adj, in_sizes[1]);
    k_zerodeg<<<gridN, T>>>(n);
    k_hist<<<gridE, T>>>(adj, e, n);
    k_assign<<<gridN, T>>>(n);
    k_scatter<<<gridE, T>>>(adj, e, n);
    k_init<<<gridW, T>>>(node_f, sidx, sval, out, n);

    int src = 0;
    for (int d = 0; d < DEPTH; d++) {
        k_eterm<<<gridW, T>>>(src, as_k, an_k, n);
        k_layer<<<gridW, T>>>(src, out, d, n);
        src ^= 1;
    }
}

// round 5
// speedup vs baseline: 1.7176x; 1.0404x over previous
#include <cuda_runtime.h>
#include <math.h>

#define NMAX 50000
#define FDIM 96
#define FD4  24          // float4s per feature row
#define EMAX 800000
#define DEPTH 3
#define OUTC 384         // (DEPTH+1)*FDIM
#define LEAKY 0.2f

// ---------------- device scratch ----------------
__device__ float4 g_fa[NMAX * FD4];
__device__ float4 g_fb[NMAX * FD4];
__device__ float4 g_eterm[NMAX];          // es0, es1, en0, en1
__device__ float2 g_sc[EMAX];             // per-edge scores / exp weights
__device__ int    g_deg[NMAX];
__device__ int    g_rowstart[NMAX];
__device__ int    g_cursor[NMAX];
__device__ int    g_csrcol[EMAX];
__device__ int    g_total;
__device__ int    g_is64;

__device__ __forceinline__ float leaky(float x) {
    return x > 0.0f ? x : LEAKY * x;
}

// ---------------- dtype detection (parallel) ----------------
__global__ void k_detect(const int* __restrict__ adj_words, int nwords) {
    __shared__ int sh[1024];
    int t = threadIdx.x;
    int acc = 0;
    int lim = min(nwords, 65536);
    for (int i = 1 + 2 * t; i < lim; i += 2048) acc |= adj_words[i];
    sh[t] = acc;
    __syncthreads();
    for (int off = 512; off > 0; off >>= 1) {
        if (t < off) sh[t] |= sh[t + off];
        __syncthreads();
    }
    if (t == 0) g_is64 = (sh[0] == 0) ? 1 : 0;
}

__global__ void k_zerodeg(int n) {
    int gid = blockIdx.x * blockDim.x + threadIdx.x;
    for (int i = gid; i < n; i += gridDim.x * blockDim.x)
        g_deg[i] = 0;
    if (gid == 0) g_total = 0;
}

// ---------------- CSR build (atomic slice assignment, no scan) ------------
__global__ void k_hist(const void* __restrict__ adj, int e, int n) {
    int is64 = g_is64;
    for (int i = blockIdx.x * blockDim.x + threadIdx.x; i < e;
         i += gridDim.x * blockDim.x) {
        int r;
        if (is64) r = (int)((const longlong2*)adj)[i].x;
        else      r = ((const int*)adj)[2 * i];
        if ((unsigned)r < (unsigned)n) atomicAdd(&g_deg[r], 1);
    }
}

__global__ void k_assign(int n) {
    for (int i = blockIdx.x * blockDim.x + threadIdx.x; i < n;
         i += gridDim.x * blockDim.x) {
        int d = g_deg[i];
        int base = atomicAdd(&g_total, d);
        g_rowstart[i] = base;
        g_cursor[i]   = base;
    }
}

__global__ void k_scatter(const void* __restrict__ adj, int e, int n) {
    int is64 = g_is64;
    for (int i = blockIdx.x * blockDim.x + threadIdx.x; i < e;
         i += gridDim.x * blockDim.x) {
        int r, c;
        if (is64) {
            longlong2 rc = ((const longlong2*)adj)[i];
            r = (int)rc.x; c = (int)rc.y;
        } else {
            int2 rc = ((const int2*)adj)[i];
            r = rc.x; c = rc.y;
        }
        if ((unsigned)r >= (unsigned)n) continue;
        if ((unsigned)c >= (unsigned)n) c = 0;
        int pos = atomicAdd(&g_cursor[r], 1);
        if (pos < EMAX) g_csrcol[pos] = c;
    }
}

// ---------------- initial features (diag rows unique -> direct store) -----
__global__ void k_init(const float* __restrict__ node_f,
                       const void* __restrict__ sidx,
                       const float* __restrict__ sval,
                       float* __restrict__ out, int n) {
    int gw = (blockIdx.x * blockDim.x + threadIdx.x) >> 5;
    int lane = threadIdx.x & 31;
    if (gw >= n) return;
    int is64 = g_is64;
    int r, c;
    if (is64) {
        longlong2 rc = ((const longlong2*)sidx)[gw];
        r = (int)rc.x; c = (int)rc.y;
    } else {
        int2 rc = ((const int2*)sidx)[gw];
        r = rc.x; c = rc.y;
    }
    if ((unsigned)r >= (unsigned)n || (unsigned)c >= (unsigned)n) return;
    if (lane >= FD4) return;
    float v = sval[gw];
    float4 s = ((const float4*)node_f)[(long)c * FD4 + lane];
    float4 x;
    x.x = fmaxf(v * s.x, 0.0f);
    x.y = fmaxf(v * s.y, 0.0f);
    x.z = fmaxf(v * s.z, 0.0f);
    x.w = fmaxf(v * s.w, 0.0f);
    g_fa[(long)r * FD4 + lane] = x;
    ((float4*)(out + (long)r * OUTC))[lane] = x;
}

// ---------------- per-node attention logits ----------------
__global__ void k_eterm(int src, const float* __restrict__ as,
                        const float* __restrict__ an, int n) {
    int gw = (blockIdx.x * blockDim.x + threadIdx.x) >> 5;
    int lane = threadIdx.x & 31;
    if (gw >= n) return;
    const float4* feat = src ? g_fb : g_fa;
    const float4* as4 = (const float4*)as;
    const float4* an4 = (const float4*)an;

    float s0 = 0.f, s1 = 0.f, n0 = 0.f, n1 = 0.f;
    if (lane < FD4) {
        float4 f = feat[(long)gw * FD4 + lane];
        float4 a;
        a = as4[lane];        s0 = f.x*a.x + f.y*a.y + f.z*a.z + f.w*a.w;
        a = as4[FD4 + lane];  s1 = f.x*a.x + f.y*a.y + f.z*a.z + f.w*a.w;
        a = an4[lane];        n0 = f.x*a.x + f.y*a.y + f.z*a.z + f.w*a.w;
        a = an4[FD4 + lane];  n1 = f.x*a.x + f.y*a.y + f.z*a.z + f.w*a.w;
    }
#pragma unroll
    for (int off = 16; off > 0; off >>= 1) {
        s0 += __shfl_xor_sync(0xffffffffu, s0, off);
        s1 += __shfl_xor_sync(0xffffffffu, s1, off);
        n0 += __shfl_xor_sync(0xffffffffu, n0, off);
        n1 += __shfl_xor_sync(0xffffffffu, n1, off);
    }
    if (lane == 0) g_eterm[gw] = make_float4(s0, s1, n0, n1);
}

// ---------------- layer: softmax + aggregate (2 heads fused) --------------
__global__ void k_layer(int src, float* __restrict__ out, int layer, int n) {
    int gw = (blockIdx.x * blockDim.x + threadIdx.x) >> 5;
    int lane = threadIdx.x & 31;
    if (gw >= n) return;
    const float4* feat = src ? g_fb : g_fa;
    float4* feat_out   = src ? g_fa : g_fb;

    int start = g_rowstart[gw];
    int end   = start + g_deg[gw];

    float4 er = g_eterm[gw];
    float es0 = er.x, es1 = er.y;

    // pass 1: gather eterm once, compute leaky scores -> scratch; track max
    float m0 = -INFINITY, m1 = -INFINITY;
    for (int j = start + lane; j < end; j += 32) {
        int c = g_csrcol[j];
        float4 ec = g_eterm[c];
        float x0 = leaky(es0 + ec.z);
        float x1 = leaky(es1 + ec.w);
        g_sc[j] = make_float2(x0, x1);
        m0 = fmaxf(m0, x0);
        m1 = fmaxf(m1, x1);
    }
#pragma unroll
    for (int off = 16; off > 0; off >>= 1) {
        m0 = fmaxf(m0, __shfl_xor_sync(0xffffffffu, m0, off));
        m1 = fmaxf(m1, __shfl_xor_sync(0xffffffffu, m1, off));
    }

    // pass 2: sequential read, exp, write back unnormalized weights
    float sum0 = 0.0f, sum1 = 0.0f;
    for (int j = start + lane; j < end; j += 32) {
        float2 s = g_sc[j];
        float e0 = __expf(s.x - m0);
        float e1 = __expf(s.y - m1);
        sum0 += e0;
        sum1 += e1;
        g_sc[j] = make_float2(e0, e1);
    }
#pragma unroll
    for (int off = 16; off > 0; off >>= 1) {
        sum0 += __shfl_xor_sync(0xffffffffu, sum0, off);
        sum1 += __shfl_xor_sync(0xffffffffu, sum1, off);
    }
    float inv0 = sum0 > 0.0f ? 1.0f / sum0 : 0.0f;
    float inv1 = sum1 > 0.0f ? 1.0f / sum1 : 0.0f;

    // pass 3: weighted aggregation; one float4 per lane covers the row
    float4 A0 = make_float4(0.f, 0.f, 0.f, 0.f);
    float4 A1 = make_float4(0.f, 0.f, 0.f, 0.f);
    bool act = (lane < FD4);
    int j = start;
    for (; j + 1 < end; j += 2) {
        int c0 = g_csrcol[j];
        int c1 = g_csrcol[j + 1];
        float2 w0 = g_sc[j];
        float2 w1 = g_sc[j + 1];
        float4 fA = make_float4(0.f, 0.f, 0.f, 0.f);
        float4 fB = make_float4(0.f, 0.f, 0.f, 0.f);
        if (act) {
            fA = feat[(long)c0 * FD4 + lane];
            fB = feat[(long)c1 * FD4 + lane];
        }
        A0.x += w0.x * fA.x + w1.x * fB.x;
        A0.y += w0.x * fA.y + w1.x * fB.y;
        A0.z += w0.x * fA.z + w1.x * fB.z;
        A0.w += w0.x * fA.w + w1.x * fB.w;
        A1.x += w0.y * fA.x + w1.y * fB.x;
        A1.y += w0.y * fA.y + w1.y * fB.y;
        A1.z += w0.y * fA.z + w1.y * fB.z;
        A1.w += w0.y * fA.w + w1.y * fB.w;
    }
    if (j < end) {
        int c0 = g_csrcol[j];
        float2 w0 = g_sc[j];
        float4 fA = make_float4(0.f, 0.f, 0.f, 0.f);
        if (act) fA = feat[(long)c0 * FD4 + lane];
        A0.x += w0.x * fA.x;  A0.y += w0.x * fA.y;
        A0.z += w0.x * fA.z;  A0.w += w0.x * fA.w;
        A1.x += w0.y * fA.x;  A1.y += w0.y * fA.y;
        A1.z += w0.y * fA.z;  A1.w += w0.y * fA.w;
    }

    if (act) {
        float4 v;
        v.x = fmaxf(0.5f * (A0.x * inv0 + A1.x * inv1), 0.0f);
        v.y = fmaxf(0.5f * (A0.y * inv0 + A1.y * inv1), 0.0f);
        v.z = fmaxf(0.5f * (A0.z * inv0 + A1.z * inv1), 0.0f);
        v.w = fmaxf(0.5f * (A0.w * inv0 + A1.w * inv1), 0.0f);
        feat_out[(long)gw * FD4 + lane] = v;
        ((float4*)(out + (long)gw * OUTC + (layer + 1) * FDIM))[lane] = v;
    }
}

// ---------------- launch ----------------
extern "C" void kernel_launch(void* const* d_in, const int* in_sizes, int n_in,
                              void* d_out, int out_size) {
    const float* node_f = (const float*)d_in[0];
    const void*  adj    = d_in[1];
    const void*  sidx   = d_in[2];
    const float* sval   = (const float*)d_in[3];
    const float* as_k   = (const float*)d_in[4];
    const float* an_k   = (const float*)d_in[5];
    float*       out    = (float*)d_out;

    int n = in_sizes[0] / FDIM;
    int e = in_sizes[1] / 2;
    if (n > NMAX) n = NMAX;
    if (e > EMAX) e = EMAX;

    const int T = 256;
    int gridN = (n + T - 1) / T;
    int gridE = (e + T - 1) / T;
    int gridW = (n + (T / 32) - 1) / (T / 32);

    k_detect<<<1, 1024>>>((const int*)adj, in_sizes[1]);
    k_zerodeg<<<gridN, T>>>(n);
    k_hist<<<gridE, T>>>(adj, e, n);
    k_assign<<<gridN, T>>>(n);
    k_scatter<<<gridE, T>>>(adj, e, n);
    k_init<<<gridW, T>>>(node_f, sidx, sval, out, n);

    int src = 0;
    for (int d = 0; d < DEPTH; d++) {
        k_eterm<<<gridW, T>>>(src, as_k, an_k, n);
        k_layer<<<gridW, T>>>(src, out, d, n);
        src ^= 1;
    }
}